// round 15
// baseline (speedup 1.0000x reference)
#include <cuda_runtime.h>
#include <cuda_fp16.h>
#include <cstdint>

// ---------------- problem constants ----------------
#define C0   12
#define D0   240
#define H0   144
#define W0   240
#define HW0  (H0*W0)
#define VV   (D0*H0*W0)          // 8,294,400 voxels
#define PIX  (480*640)           // 307,200 pixels

#define D1 120
#define H1 72
#define W1 120
#define N1 (D1*H1*W1)

#define D2 60
#define H2 36
#define W2 60
#define N2 (D2*H2*W2)

#define ZCH 12
#define ZL  (D0/ZCH)             // 20

#define NEG_INF (__int_as_float(0xff800000))

typedef unsigned long long ull;

// ---------------- f32x2 helpers ----------------
__device__ __forceinline__ ull pk2(float lo, float hi) {
    ull r;
    asm("mov.b64 %0,{%1,%2};" : "=l"(r) : "r"(__float_as_uint(lo)), "r"(__float_as_uint(hi)));
    return r;
}
__device__ __forceinline__ float2 upk2(ull v) {
    unsigned lo, hi;
    asm("mov.b64 {%0,%1},%2;" : "=r"(lo), "=r"(hi) : "l"(v));
    return make_float2(__uint_as_float(lo), __uint_as_float(hi));
}
__device__ __forceinline__ ull fma2(ull a, ull b, ull c) {
    ull d;
    asm("fma.rn.f32x2 %0,%1,%2,%3;" : "=l"(d) : "l"(a), "l"(b), "l"(c));
    return d;
}

// ---------------- scratch ----------------
__device__ __half g_filled[(size_t)C0*VV];   // fp16
__device__ int    g_winner[VV];
__device__ __half g_ds1[(size_t)16*N1];      // fp16
__device__ float  g_t0[(size_t)4*N1];
__device__ float  g_t1[(size_t)4*N1];
__device__ float  g_t2[(size_t)4*N1];
__device__ __half g_bn1[(size_t)16*N1];      // fp16
__device__ float  g_ds2[(size_t)32*N2];
__device__ float  g_u0[(size_t)8*N2];
__device__ float  g_u1[(size_t)8*N2];
__device__ float  g_u2[(size_t)8*N2];

// ---------------- generic load/store helpers ----------------
__device__ __forceinline__ float4 ld4f(const float* p) { return *(const float4*)p; }
__device__ __forceinline__ float4 ld4f(const __half* p) {
    uint2 u = *(const uint2*)p;
    float2 a = __half22float2(*reinterpret_cast<const __half2*>(&u.x));
    float2 b = __half22float2(*reinterpret_cast<const __half2*>(&u.y));
    return make_float4(a.x, a.y, b.x, b.y);
}
__device__ __forceinline__ void st4(float* p, float4 v) { *(float4*)p = v; }
__device__ __forceinline__ void st4(__half* p, float4 v) {
    union { __half2 h[2]; uint2 u; } pk_;
    pk_.h[0] = __floats2half2_rn(v.x, v.y);
    pk_.h[1] = __floats2half2_rn(v.z, v.w);
    *(uint2*)p = pk_.u;
}

// 9-value row loaders (zero-padded left edge)
__device__ __forceinline__ void load_row9(const float* r, bool lx, float v[9]) {
    float4 a = *(const float4*)r;
    float4 b = *(const float4*)(r + 4);
    v[0] = lx ? r[-1] : 0.f;
    v[1]=a.x; v[2]=a.y; v[3]=a.z; v[4]=a.w;
    v[5]=b.x; v[6]=b.y; v[7]=b.z; v[8]=b.w;
}
__device__ __forceinline__ void load_row9(const __half* r, bool lx, float v[9]) {
    uint4 u = *(const uint4*)r;          // 8 halves, 16B-aligned
    float2 p0 = __half22float2(*reinterpret_cast<const __half2*>(&u.x));
    float2 p1 = __half22float2(*reinterpret_cast<const __half2*>(&u.y));
    float2 p2 = __half22float2(*reinterpret_cast<const __half2*>(&u.z));
    float2 p3 = __half22float2(*reinterpret_cast<const __half2*>(&u.w));
    v[0] = lx ? __half2float(r[-1]) : 0.f;
    v[1]=p0.x; v[2]=p0.y; v[3]=p1.x; v[4]=p1.y;
    v[5]=p2.x; v[6]=p2.y; v[7]=p3.x; v[8]=p3.y;
}

// ---------------- scatter stage ----------------
__global__ void k_init_w() {
    int i = blockIdx.x * blockDim.x + threadIdx.x;
    if (i < VV/4) ((int4*)g_winner)[i] = make_int4(-1,-1,-1,-1);
}

__global__ void k_winner(const int* __restrict__ depth) {
    int p = blockIdx.x * blockDim.x + threadIdx.x;
    if (p >= PIX) return;
    int d = depth[p];
    if (d > 0) atomicMax(&g_winner[d], p);
}

// ---------------- avgpool fill, gather version (ZCH=12, fp16 output) -------
__global__ void k_fill_g(const float* __restrict__ feat) {
    const int XQ = W0/4;   // 60
    int gid = blockIdx.x * blockDim.x + threadIdx.x;
    if (gid >= C0*H0*XQ*ZCH) return;
    int xq = gid % XQ;
    int y  = (gid / XQ) % H0;
    int zc = (gid / (XQ*H0)) % ZCH;
    int c  = gid / (XQ*H0*ZCH);
    int x0 = xq * 4;
    int z0 = zc * ZL;

    const int*   wbase = g_winner;
    const float* featc = feat + (size_t)c*PIX;
    __half*      outb  = g_filled + (size_t)c*VV;

    bool ym0 = (y > 0), ym2 = (y < H0-1);
    int ro0 = (y-1)*W0 + x0;
    int ro1 =  y   *W0 + x0;
    int ro2 = (y+1)*W0 + x0;
    bool lx = (x0 > 0), rx = (x0 + 4 < W0);

    auto val = [&](int wv) -> float {
        return (wv >= 0) ? __ldg(featc + wv) : 0.f;
    };

    auto plane = [&](int z, float4& s, float4& ctr) {
        const int* pl = wbase + (size_t)z*HW0;
        s = make_float4(0.f,0.f,0.f,0.f);
        #pragma unroll
        for (int dy = 0; dy < 3; dy++) {
            if (dy == 0 && !ym0) continue;
            if (dy == 2 && !ym2) continue;
            const int* r = pl + (dy == 0 ? ro0 : (dy == 1 ? ro1 : ro2));
            int4 mi = *(const int4*)r;
            float m0 = val(mi.x), m1 = val(mi.y), m2 = val(mi.z), m3 = val(mi.w);
            float a = lx ? val(__ldg(r-1)) : 0.f;
            float b = rx ? val(__ldg(r+4)) : 0.f;
            s.x += a  + m0 + m1;
            s.y += m0 + m1 + m2;
            s.z += m1 + m2 + m3;
            s.w += m2 + m3 + b;
            if (dy == 1) ctr = make_float4(m0, m1, m2, m3);
        }
    };

    float4 sp, sc, sn, cc_, cn, dum;
    const float4 z4 = make_float4(0.f,0.f,0.f,0.f);
    if (z0 > 0) plane(z0-1, sp, dum); else sp = z4;
    plane(z0, sc, cc_);
    for (int z = z0; z < z0 + ZL; z++) {
        if (z + 1 < D0) plane(z+1, sn, cn); else { sn = z4; cn = z4; }
        float4 o;
        o.x = (cc_.x == 0.f) ? (sp.x+sc.x+sn.x) * (1.f/27.f) : cc_.x;
        o.y = (cc_.y == 0.f) ? (sp.y+sc.y+sn.y) * (1.f/27.f) : cc_.y;
        o.z = (cc_.z == 0.f) ? (sp.z+sc.z+sn.z) * (1.f/27.f) : cc_.z;
        o.w = (cc_.w == 0.f) ? (sp.w+sc.w+sn.w) * (1.f/27.f) : cc_.w;
        st4(outb + (size_t)z*HW0 + ro1, o);
        sp = sc; sc = sn; cc_ = cn;
    }
}

// ---------------- stage-1 downsample + 1x1 w_in, FFMA2 inner loop ----------
// Weights pre-packed (w,w) in smem (10.6KB) -> LDS.64 feeds fma.rn.f32x2.
template<int CIN, int CC, int C2, int MAXB>
__global__ void __launch_bounds__(256, MAXB)
k_down_f2x(const __half* __restrict__ in, const float* __restrict__ w,
           const float* __restrict__ win,
           __half* __restrict__ out, float* __restrict__ t0,
           int Dd, int Hh, int Ww, int Hin, int Win) {
    extern __shared__ float sw[];
    const int NW1 = CC*CIN*27;
    const int NW2 = C2*(CC+CIN);
    for (int i = threadIdx.x; i < NW1; i += blockDim.x) {
        float wv = w[i];
        sw[2*i] = wv; sw[2*i+1] = wv;
    }
    for (int i = threadIdx.x; i < NW2; i += blockDim.x) sw[2*NW1+i] = win[i];
    __syncthreads();
    const float* swin = sw + 2*NW1;

    const int XQ = Ww/4;
    int N = Dd*Hh*Ww;
    int gid = blockIdx.x * blockDim.x + threadIdx.x;
    if (gid >= Dd*Hh*XQ) return;
    int xq = gid % XQ;
    int y  = (gid / XQ) % Hh;
    int z  = gid / (XQ*Hh);
    int x0 = xq * 4;
    size_t HWin = (size_t)Hin*Win;
    size_t Vin  = (size_t)(2*Dd)*HWin;
    bool lx = (x0 > 0);
    int outpos = (z*Hh + y)*Ww + x0;

    ull acc01[CC], acc23[CC];
    #pragma unroll
    for (int o = 0; o < CC; o++) { acc01[o] = 0ull; acc23[o] = 0ull; }

    for (int ic = 0; ic < CIN; ic++) {
        const __half* inp = in + (size_t)ic*Vin;
        float m[4] = {NEG_INF, NEG_INF, NEG_INF, NEG_INF};
        #pragma unroll
        for (int dz = 0; dz < 3; dz++) {
            int iz = 2*z - 1 + dz;
            if (iz < 0) continue;
            #pragma unroll
            for (int dy = 0; dy < 3; dy++) {
                int iy = 2*y - 1 + dy;
                if (iy < 0) continue;
                const __half* r = inp + (size_t)iz*HWin + (size_t)iy*Win + 2*x0;
                float v[9];
                load_row9(r, lx, v);
                int wb = ic*27 + dz*9 + dy*3;
                #pragma unroll
                for (int dx = 0; dx < 3; dx++) {
                    ull p01 = pk2(v[dx],   v[dx+2]);
                    ull p23 = pk2(v[dx+4], v[dx+6]);
                    #pragma unroll
                    for (int o = 0; o < CC; o++) {
                        ull wd = *(const ull*)&sw[2*(o*CIN*27 + wb + dx)];
                        acc01[o] = fma2(p01, wd, acc01[o]);
                        acc23[o] = fma2(p23, wd, acc23[o]);
                    }
                }
                if (dz > 0 && dy > 0) {
                    #pragma unroll
                    for (int i = 0; i < 4; i++)
                        m[i] = fmaxf(m[i], fmaxf(v[2*i+1], v[2*i+2]));
                }
            }
        }
        st4(out + (size_t)(CC + ic)*N + outpos,
            make_float4(fmaxf(m[0],0.f), fmaxf(m[1],0.f), fmaxf(m[2],0.f), fmaxf(m[3],0.f)));
    }

    float tac[C2][4];
    #pragma unroll
    for (int c = 0; c < C2; c++)
        #pragma unroll
        for (int i = 0; i < 4; i++) tac[c][i] = 0.f;

    #pragma unroll
    for (int o = 0; o < CC; o++) {
        float2 a = upk2(acc01[o]), b = upk2(acc23[o]);
        float cv[4] = {fmaxf(a.x,0.f), fmaxf(a.y,0.f), fmaxf(b.x,0.f), fmaxf(b.y,0.f)};
        st4(out + (size_t)o*N + outpos, make_float4(cv[0],cv[1],cv[2],cv[3]));
        #pragma unroll
        for (int c = 0; c < C2; c++) {
            float wv = swin[c*(CC+CIN) + o];
            #pragma unroll
            for (int i = 0; i < 4; i++) tac[c][i] = fmaf(wv, cv[i], tac[c][i]);
        }
    }
    for (int ic = 0; ic < CIN; ic++) {
        float4 p4 = ld4f(out + (size_t)(CC + ic)*N + outpos);
        float p[4] = {p4.x, p4.y, p4.z, p4.w};
        #pragma unroll
        for (int c = 0; c < C2; c++) {
            float wv = swin[c*(CC+CIN) + CC + ic];
            #pragma unroll
            for (int i = 0; i < 4; i++) tac[c][i] = fmaf(wv, p[i], tac[c][i]);
        }
    }
    #pragma unroll
    for (int c = 0; c < C2; c++)
        st4(t0 + (size_t)c*N + outpos,
            make_float4(fmaxf(tac[c][0],0.f), fmaxf(tac[c][1],0.f),
                        fmaxf(tac[c][2],0.f), fmaxf(tac[c][3],0.f)));
}

// ---------------- stage-2 downsample + 1x1 w_in (r12 proven scalar) --------
template<typename TIN, typename TOUT, int CIN, int CC, int C2, int MAXB>
__global__ void __launch_bounds__(256, MAXB)
k_down_f(const TIN* __restrict__ in, const float* __restrict__ w,
         const float* __restrict__ win,
         TOUT* __restrict__ out, float* __restrict__ t0,
         int Dd, int Hh, int Ww, int Hin, int Win) {
    extern __shared__ float sw[];
    const int NW1 = CC*CIN*27;
    const int NW2 = C2*(CC+CIN);
    for (int i = threadIdx.x; i < NW1; i += blockDim.x) sw[i] = w[i];
    for (int i = threadIdx.x; i < NW2; i += blockDim.x) sw[NW1+i] = win[i];
    __syncthreads();
    const float* swin = sw + NW1;

    const int XQ = Ww/4;
    int N = Dd*Hh*Ww;
    int gid = blockIdx.x * blockDim.x + threadIdx.x;
    if (gid >= Dd*Hh*XQ) return;
    int xq = gid % XQ;
    int y  = (gid / XQ) % Hh;
    int z  = gid / (XQ*Hh);
    int x0 = xq * 4;
    size_t HWin = (size_t)Hin*Win;
    size_t Vin  = (size_t)(2*Dd)*HWin;
    bool lx = (x0 > 0);
    int outpos = (z*Hh + y)*Ww + x0;

    float acc[CC][4];
    #pragma unroll
    for (int o = 0; o < CC; o++)
        #pragma unroll
        for (int i = 0; i < 4; i++) acc[o][i] = 0.f;

    for (int ic = 0; ic < CIN; ic++) {
        const TIN* inp = in + (size_t)ic*Vin;
        float m[4] = {NEG_INF, NEG_INF, NEG_INF, NEG_INF};
        #pragma unroll
        for (int dz = 0; dz < 3; dz++) {
            int iz = 2*z - 1 + dz;
            if (iz < 0) continue;
            #pragma unroll
            for (int dy = 0; dy < 3; dy++) {
                int iy = 2*y - 1 + dy;
                if (iy < 0) continue;
                const TIN* r = inp + (size_t)iz*HWin + (size_t)iy*Win + 2*x0;
                float v[9];
                load_row9(r, lx, v);
                int wb = ic*27 + dz*9 + dy*3;
                #pragma unroll
                for (int o = 0; o < CC; o++) {
                    float w0 = sw[o*CIN*27 + wb + 0];
                    float w1 = sw[o*CIN*27 + wb + 1];
                    float w2 = sw[o*CIN*27 + wb + 2];
                    acc[o][0] = fmaf(w0, v[0], fmaf(w1, v[1], fmaf(w2, v[2], acc[o][0])));
                    acc[o][1] = fmaf(w0, v[2], fmaf(w1, v[3], fmaf(w2, v[4], acc[o][1])));
                    acc[o][2] = fmaf(w0, v[4], fmaf(w1, v[5], fmaf(w2, v[6], acc[o][2])));
                    acc[o][3] = fmaf(w0, v[6], fmaf(w1, v[7], fmaf(w2, v[8], acc[o][3])));
                }
                if (dz > 0 && dy > 0) {
                    #pragma unroll
                    for (int i = 0; i < 4; i++)
                        m[i] = fmaxf(m[i], fmaxf(v[2*i+1], v[2*i+2]));
                }
            }
        }
        st4(out + (size_t)(CC + ic)*N + outpos,
            make_float4(fmaxf(m[0],0.f), fmaxf(m[1],0.f), fmaxf(m[2],0.f), fmaxf(m[3],0.f)));
    }

    float tac[C2][4];
    #pragma unroll
    for (int c = 0; c < C2; c++)
        #pragma unroll
        for (int i = 0; i < 4; i++) tac[c][i] = 0.f;

    #pragma unroll
    for (int o = 0; o < CC; o++) {
        float cv[4];
        #pragma unroll
        for (int i = 0; i < 4; i++) cv[i] = fmaxf(acc[o][i], 0.f);
        st4(out + (size_t)o*N + outpos, make_float4(cv[0],cv[1],cv[2],cv[3]));
        #pragma unroll
        for (int c = 0; c < C2; c++) {
            float wv = swin[c*(CC+CIN) + o];
            #pragma unroll
            for (int i = 0; i < 4; i++) tac[c][i] = fmaf(wv, cv[i], tac[c][i]);
        }
    }
    for (int ic = 0; ic < CIN; ic++) {
        float4 p4 = ld4f(out + (size_t)(CC + ic)*N + outpos);
        float p[4] = {p4.x, p4.y, p4.z, p4.w};
        #pragma unroll
        for (int c = 0; c < C2; c++) {
            float wv = swin[c*(CC+CIN) + CC + ic];
            #pragma unroll
            for (int i = 0; i < 4; i++) tac[c][i] = fmaf(wv, p[i], tac[c][i]);
        }
    }
    #pragma unroll
    for (int c = 0; c < C2; c++)
        st4(t0 + (size_t)c*N + outpos,
            make_float4(fmaxf(tac[c][0],0.f), fmaxf(tac[c][1],0.f),
                        fmaxf(tac[c][2],0.f), fmaxf(tac[c][3],0.f)));
}

// ---------------- vectorized bottleneck conv (fp32, r12 proven) ------------
template<int CIN, int COUT, int KD, int KH, int KW, bool ADD>
__global__ void k_conv3_v(const float* __restrict__ in, const float* __restrict__ w,
                          const float* __restrict__ bias, const float* __restrict__ add1,
                          float* __restrict__ out, int Dd, int Hh, int Ww) {
    constexpr int KSZ = KD*KH*KW;
    __shared__ float sw[COUT*CIN*KSZ];
    __shared__ float sb[COUT];
    for (int i = threadIdx.x; i < COUT*CIN*KSZ; i += blockDim.x) sw[i] = w[i];
    if (threadIdx.x < COUT) sb[threadIdx.x] = bias ? bias[threadIdx.x] : 0.f;
    __syncthreads();

    const int XQ = Ww/4;
    int N = Dd*Hh*Ww;
    int gid = blockIdx.x * blockDim.x + threadIdx.x;
    if (gid >= Dd*Hh*XQ) return;
    int xq = gid % XQ;
    int y  = (gid / XQ) % Hh;
    int z  = gid / (XQ*Hh);
    int x0 = xq * 4;
    bool lx = (x0 > 0), rxv = (x0 + 4 < Ww);
    int pos = (z*Hh + y)*Ww + x0;

    float acc[COUT][4];
    #pragma unroll
    for (int o = 0; o < COUT; o++)
        #pragma unroll
        for (int i = 0; i < 4; i++) acc[o][i] = sb[o];

    for (int ic = 0; ic < CIN; ic++) {
        const float* base = in + (size_t)ic*N;
        #pragma unroll
        for (int dz = 0; dz < KD; dz++) {
            int iz = z - KD/2 + dz;
            bool zv = ((unsigned)iz < (unsigned)Dd);
            #pragma unroll
            for (int dy = 0; dy < KH; dy++) {
                int iy = y - KH/2 + dy;
                bool rv = zv && ((unsigned)iy < (unsigned)Hh);
                const float* r = base + ((size_t)(zv?iz:0)*Hh + (rv?iy:0))*Ww + x0;
                float4 mv = rv ? *(const float4*)r : make_float4(0,0,0,0);
                if (KW == 3) {
                    float aE = (rv && lx)  ? r[-1] : 0.f;
                    float bE = (rv && rxv) ? r[4]  : 0.f;
                    float v[6] = {aE, mv.x, mv.y, mv.z, mv.w, bE};
                    #pragma unroll
                    for (int o = 0; o < COUT; o++) {
                        const float* wr = &sw[(o*CIN + ic)*KSZ + (dz*KH + dy)*KW];
                        float w0 = wr[0], w1 = wr[1], w2 = wr[2];
                        #pragma unroll
                        for (int i = 0; i < 4; i++)
                            acc[o][i] = fmaf(w0, v[i], fmaf(w1, v[i+1], fmaf(w2, v[i+2], acc[o][i])));
                    }
                } else {
                    float v[4] = {mv.x, mv.y, mv.z, mv.w};
                    #pragma unroll
                    for (int o = 0; o < COUT; o++) {
                        float wv = sw[(o*CIN + ic)*KSZ + (dz*KH + dy)];
                        #pragma unroll
                        for (int i = 0; i < 4; i++)
                            acc[o][i] = fmaf(wv, v[i], acc[o][i]);
                    }
                }
            }
        }
    }
    #pragma unroll
    for (int o = 0; o < COUT; o++) {
        float r4[4];
        #pragma unroll
        for (int i = 0; i < 4; i++) r4[i] = acc[o][i];
        if (ADD) {
            float4 ad = *(const float4*)(add1 + (size_t)o*N + pos);
            r4[0] += ad.x; r4[1] += ad.y; r4[2] += ad.z; r4[3] += ad.w;
        }
        *(float4*)(out + (size_t)o*N + pos) =
            make_float4(fmaxf(r4[0],0.f), fmaxf(r4[1],0.f), fmaxf(r4[2],0.f), fmaxf(r4[3],0.f));
    }
}

// ---------------- conv313 + 1x1 w_out + residual, fused --------------------
template<int CIN, int OC2, typename TR, typename TO>
__global__ void k_conv_out_v(const float* __restrict__ in, const float* __restrict__ w,
                             const float* __restrict__ bias,
                             const float* __restrict__ add1, const float* __restrict__ add2,
                             const float* __restrict__ wout, const TR* __restrict__ resid,
                             TO* __restrict__ out, int Dd, int Hh, int Ww) {
    __shared__ float sw[CIN*CIN*9];
    __shared__ float swo[OC2*CIN];
    __shared__ float sb[CIN];
    for (int i = threadIdx.x; i < CIN*CIN*9; i += blockDim.x) sw[i] = w[i];
    for (int i = threadIdx.x; i < OC2*CIN; i += blockDim.x) swo[i] = wout[i];
    if (threadIdx.x < CIN) sb[threadIdx.x] = bias[threadIdx.x];
    __syncthreads();

    const int XQ = Ww/4;
    int N = Dd*Hh*Ww;
    int gid = blockIdx.x * blockDim.x + threadIdx.x;
    if (gid >= Dd*Hh*XQ) return;
    int xq = gid % XQ;
    int y  = (gid / XQ) % Hh;
    int z  = gid / (XQ*Hh);
    int x0 = xq * 4;
    bool lx = (x0 > 0), rxv = (x0 + 4 < Ww);
    int pos = (z*Hh + y)*Ww + x0;

    float acc[CIN][4];
    #pragma unroll
    for (int o = 0; o < CIN; o++)
        #pragma unroll
        for (int i = 0; i < 4; i++) acc[o][i] = sb[o];

    for (int ic = 0; ic < CIN; ic++) {
        const float* base = in + (size_t)ic*N;
        #pragma unroll
        for (int dz = 0; dz < 3; dz++) {           // kernel (3,1,3)
            int iz = z - 1 + dz;
            bool rv = ((unsigned)iz < (unsigned)Dd);
            const float* r = base + ((size_t)(rv?iz:0)*Hh + y)*Ww + x0;
            float4 mv = rv ? *(const float4*)r : make_float4(0,0,0,0);
            float aE = (rv && lx)  ? r[-1] : 0.f;
            float bE = (rv && rxv) ? r[4]  : 0.f;
            float v[6] = {aE, mv.x, mv.y, mv.z, mv.w, bE};
            #pragma unroll
            for (int o = 0; o < CIN; o++) {
                const float* wr = &sw[(o*CIN + ic)*9 + dz*3];
                float w0 = wr[0], w1 = wr[1], w2 = wr[2];
                #pragma unroll
                for (int i = 0; i < 4; i++)
                    acc[o][i] = fmaf(w0, v[i], fmaf(w1, v[i+1], fmaf(w2, v[i+2], acc[o][i])));
            }
        }
    }
    float yv[CIN][4];
    #pragma unroll
    for (int o = 0; o < CIN; o++) {
        float4 a1 = *(const float4*)(add1 + (size_t)o*N + pos);
        float4 a2 = *(const float4*)(add2 + (size_t)o*N + pos);
        yv[o][0] = fmaxf(acc[o][0] + a1.x + a2.x, 0.f);
        yv[o][1] = fmaxf(acc[o][1] + a1.y + a2.y, 0.f);
        yv[o][2] = fmaxf(acc[o][2] + a1.z + a2.z, 0.f);
        yv[o][3] = fmaxf(acc[o][3] + a1.w + a2.w, 0.f);
    }
    #pragma unroll
    for (int o2 = 0; o2 < OC2; o2++) {
        float4 rr = ld4f(resid + (size_t)o2*N + pos);
        float s[4] = {rr.x, rr.y, rr.z, rr.w};
        #pragma unroll
        for (int c = 0; c < CIN; c++) {
            float wv = swo[o2*CIN + c];
            #pragma unroll
            for (int i = 0; i < 4; i++) s[i] = fmaf(wv, yv[c][i], s[i]);
        }
        st4(out + (size_t)o2*N + pos,
            make_float4(fmaxf(s[0],0.f), fmaxf(s[1],0.f), fmaxf(s[2],0.f), fmaxf(s[3],0.f)));
    }
}

// ---------------- launch ----------------
static inline int gridFor(long n, int b) { return (int)((n + b - 1) / b); }

extern "C" void kernel_launch(void* const* d_in, const int* in_sizes, int n_in,
                              void* d_out, int out_size) {
    const float* feat    = (const float*)d_in[0];
    const int*   depth   = (const int*)  d_in[1];
    const float* w_ds1   = (const float*)d_in[2];
    const float* b1_win  = (const float*)d_in[3];
    const float* b1_w133 = (const float*)d_in[4];
    const float* b1_b133 = (const float*)d_in[5];
    const float* b1_w331 = (const float*)d_in[6];
    const float* b1_b331 = (const float*)d_in[7];
    const float* b1_w313 = (const float*)d_in[8];
    const float* b1_b313 = (const float*)d_in[9];
    const float* b1_wout = (const float*)d_in[10];
    const float* w_ds2   = (const float*)d_in[11];
    const float* b2_win  = (const float*)d_in[12];
    const float* b2_w133 = (const float*)d_in[13];
    const float* b2_b133 = (const float*)d_in[14];
    const float* b2_w331 = (const float*)d_in[15];
    const float* b2_b331 = (const float*)d_in[16];
    const float* b2_w313 = (const float*)d_in[17];
    const float* b2_b313 = (const float*)d_in[18];
    const float* b2_wout = (const float*)d_in[19];
    float* out = (float*)d_out;

    void *a0,*a1,*a2,*a3,*a4,*a5,*a6,*a7,*a8,*a9;
    cudaGetSymbolAddress(&a0, g_filled);
    cudaGetSymbolAddress(&a1, g_ds1);
    cudaGetSymbolAddress(&a2, g_t0);
    cudaGetSymbolAddress(&a3, g_t1);
    cudaGetSymbolAddress(&a4, g_t2);
    cudaGetSymbolAddress(&a5, g_bn1);
    cudaGetSymbolAddress(&a6, g_ds2);
    cudaGetSymbolAddress(&a7, g_u0);
    cudaGetSymbolAddress(&a8, g_u1);
    cudaGetSymbolAddress(&a9, g_u2);
    __half* p_filled = (__half*)a0;
    __half* p_ds1 = (__half*)a1;
    float* p_t0  = (float*)a2; float* p_t1 = (float*)a3; float* p_t2 = (float*)a4;
    __half* p_bn1 = (__half*)a5;
    float* p_ds2 = (float*)a6;
    float* p_u0  = (float*)a7; float* p_u1 = (float*)a8; float* p_u2 = (float*)a9;

    // scatter stage
    k_init_w <<<gridFor(VV/4, 256), 256>>>();
    k_winner <<<gridFor(PIX, 256), 256>>>(depth);

    // avgpool fill via gather (fp16 output)
    k_fill_g<<<gridFor((long)C0*H0*(W0/4)*ZCH, 256), 256>>>(feat);

    // stage 1 (FFMA2 downsample, 10.6KB smem)
    k_down_f2x<12,4,4,4><<<gridFor((long)D1*H1*(W1/4), 256), 256,
                           (2*4*12*27 + 4*16)*sizeof(float)>>>(
        p_filled, w_ds1, b1_win, p_ds1, p_t0, D1, H1, W1, H0, W0);
    k_conv3_v<4,4,1,3,3,false><<<gridFor(N1/4, 256), 256>>>(
        p_t0, b1_w133, b1_b133, nullptr, p_t1, D1, H1, W1);
    k_conv3_v<4,4,3,3,1,true><<<gridFor(N1/4, 256), 256>>>(
        p_t1, b1_w331, b1_b331, p_t1, p_t2, D1, H1, W1);
    k_conv_out_v<4,16,__half,__half><<<gridFor(N1/4, 256), 256>>>(
        p_t2, b1_w313, b1_b313, p_t2, p_t1, b1_wout, p_ds1, p_bn1, D1, H1, W1);

    // stage 2 (scalar downsample, r12 proven; 27.6KB smem)
    k_down_f<__half,float,16,16,8,2><<<gridFor((long)D2*H2*(W2/4), 256), 256,
                                      (16*16*27 + 8*32)*sizeof(float)>>>(
        p_bn1, w_ds2, b2_win, p_ds2, p_u0, D2, H2, W2, H1, W1);
    k_conv3_v<8,8,1,3,3,false><<<gridFor(N2/4, 128), 128>>>(
        p_u0, b2_w133, b2_b133, nullptr, p_u1, D2, H2, W2);
    k_conv3_v<8,8,3,3,1,true><<<gridFor(N2/4, 128), 128>>>(
        p_u1, b2_w331, b2_b331, p_u1, p_u2, D2, H2, W2);
    k_conv_out_v<8,32,float,float><<<gridFor(N2/4, 128), 128>>>(
        p_u2, b2_w313, b2_b313, p_u2, p_u1, b2_wout, p_ds2, out, D2, H2, W2);
}

// round 16
// speedup vs baseline: 1.0496x; 1.0496x over previous
#include <cuda_runtime.h>
#include <cuda_fp16.h>
#include <cstdint>

// ---------------- problem constants ----------------
#define C0   12
#define D0   240
#define H0   144
#define W0   240
#define HW0  (H0*W0)
#define VV   (D0*H0*W0)          // 8,294,400 voxels
#define PIX  (480*640)           // 307,200 pixels

#define D1 120
#define H1 72
#define W1 120
#define N1 (D1*H1*W1)

#define D2 60
#define H2 36
#define W2 60
#define N2 (D2*H2*W2)

#define ZCH 12
#define ZL  (D0/ZCH)             // 20

#define NEG_INF (__int_as_float(0xff800000))

// ---------------- scratch ----------------
__device__ __half g_filled[(size_t)C0*VV];   // fp16
__device__ int    g_winner[VV];
__device__ __half g_ds1[(size_t)16*N1];      // fp16
__device__ float  g_t0[(size_t)4*N1];
__device__ float  g_t1[(size_t)4*N1];
__device__ float  g_t2[(size_t)4*N1];
__device__ __half g_bn1[(size_t)16*N1];      // fp16
__device__ float  g_ds2[(size_t)32*N2];
__device__ float  g_u0[(size_t)8*N2];
__device__ float  g_u1[(size_t)8*N2];
__device__ float  g_u2[(size_t)8*N2];

// ---------------- generic load/store helpers ----------------
__device__ __forceinline__ float4 ld4f(const float* p) { return *(const float4*)p; }
__device__ __forceinline__ float4 ld4f(const __half* p) {
    uint2 u = *(const uint2*)p;
    float2 a = __half22float2(*reinterpret_cast<const __half2*>(&u.x));
    float2 b = __half22float2(*reinterpret_cast<const __half2*>(&u.y));
    return make_float4(a.x, a.y, b.x, b.y);
}
__device__ __forceinline__ void st4(float* p, float4 v) { *(float4*)p = v; }
__device__ __forceinline__ void st4(__half* p, float4 v) {
    union { __half2 h[2]; uint2 u; } pk_;
    pk_.h[0] = __floats2half2_rn(v.x, v.y);
    pk_.h[1] = __floats2half2_rn(v.z, v.w);
    *(uint2*)p = pk_.u;
}

// 9-value row loaders (zero-padded left edge)
__device__ __forceinline__ void load_row9(const float* r, bool lx, float v[9]) {
    float4 a = *(const float4*)r;
    float4 b = *(const float4*)(r + 4);
    v[0] = lx ? r[-1] : 0.f;
    v[1]=a.x; v[2]=a.y; v[3]=a.z; v[4]=a.w;
    v[5]=b.x; v[6]=b.y; v[7]=b.z; v[8]=b.w;
}
__device__ __forceinline__ void load_row9(const __half* r, bool lx, float v[9]) {
    uint4 u = *(const uint4*)r;          // 8 halves, 16B-aligned
    float2 p0 = __half22float2(*reinterpret_cast<const __half2*>(&u.x));
    float2 p1 = __half22float2(*reinterpret_cast<const __half2*>(&u.y));
    float2 p2 = __half22float2(*reinterpret_cast<const __half2*>(&u.z));
    float2 p3 = __half22float2(*reinterpret_cast<const __half2*>(&u.w));
    v[0] = lx ? __half2float(r[-1]) : 0.f;
    v[1]=p0.x; v[2]=p0.y; v[3]=p1.x; v[4]=p1.y;
    v[5]=p2.x; v[6]=p2.y; v[7]=p3.x; v[8]=p3.y;
}

// ---------------- scatter stage ----------------
__global__ void k_init_w() {
    int i = blockIdx.x * blockDim.x + threadIdx.x;
    if (i < VV/4) ((int4*)g_winner)[i] = make_int4(-1,-1,-1,-1);
}

__global__ void k_winner(const int* __restrict__ depth) {
    int p = blockIdx.x * blockDim.x + threadIdx.x;
    if (p >= PIX) return;
    int d = depth[p];
    if (d > 0) atomicMax(&g_winner[d], p);
}

// ---------------- avgpool fill, gather version (ZCH=12, fp16 output) -------
__global__ void k_fill_g(const float* __restrict__ feat) {
    const int XQ = W0/4;   // 60
    int gid = blockIdx.x * blockDim.x + threadIdx.x;
    if (gid >= C0*H0*XQ*ZCH) return;
    int xq = gid % XQ;
    int y  = (gid / XQ) % H0;
    int zc = (gid / (XQ*H0)) % ZCH;
    int c  = gid / (XQ*H0*ZCH);
    int x0 = xq * 4;
    int z0 = zc * ZL;

    const int*   wbase = g_winner;
    const float* featc = feat + (size_t)c*PIX;
    __half*      outb  = g_filled + (size_t)c*VV;

    bool ym0 = (y > 0), ym2 = (y < H0-1);
    int ro0 = (y-1)*W0 + x0;
    int ro1 =  y   *W0 + x0;
    int ro2 = (y+1)*W0 + x0;
    bool lx = (x0 > 0), rx = (x0 + 4 < W0);

    auto val = [&](int wv) -> float {
        return (wv >= 0) ? __ldg(featc + wv) : 0.f;
    };

    auto plane = [&](int z, float4& s, float4& ctr) {
        const int* pl = wbase + (size_t)z*HW0;
        s = make_float4(0.f,0.f,0.f,0.f);
        #pragma unroll
        for (int dy = 0; dy < 3; dy++) {
            if (dy == 0 && !ym0) continue;
            if (dy == 2 && !ym2) continue;
            const int* r = pl + (dy == 0 ? ro0 : (dy == 1 ? ro1 : ro2));
            int4 mi = *(const int4*)r;
            float m0 = val(mi.x), m1 = val(mi.y), m2 = val(mi.z), m3 = val(mi.w);
            float a = lx ? val(__ldg(r-1)) : 0.f;
            float b = rx ? val(__ldg(r+4)) : 0.f;
            s.x += a  + m0 + m1;
            s.y += m0 + m1 + m2;
            s.z += m1 + m2 + m3;
            s.w += m2 + m3 + b;
            if (dy == 1) ctr = make_float4(m0, m1, m2, m3);
        }
    };

    float4 sp, sc, sn, cc_, cn, dum;
    const float4 z4 = make_float4(0.f,0.f,0.f,0.f);
    if (z0 > 0) plane(z0-1, sp, dum); else sp = z4;
    plane(z0, sc, cc_);
    for (int z = z0; z < z0 + ZL; z++) {
        if (z + 1 < D0) plane(z+1, sn, cn); else { sn = z4; cn = z4; }
        float4 o;
        o.x = (cc_.x == 0.f) ? (sp.x+sc.x+sn.x) * (1.f/27.f) : cc_.x;
        o.y = (cc_.y == 0.f) ? (sp.y+sc.y+sn.y) * (1.f/27.f) : cc_.y;
        o.z = (cc_.z == 0.f) ? (sp.z+sc.z+sn.z) * (1.f/27.f) : cc_.z;
        o.w = (cc_.w == 0.f) ? (sp.w+sc.w+sn.w) * (1.f/27.f) : cc_.w;
        st4(outb + (size_t)z*HW0 + ro1, o);
        sp = sc; sc = sn; cc_ = cn;
    }
}

// ---------------- fused downsample + 1x1 w_in (transposed weights) ---------
// smem weights laid out [ic][dz][dy][dx][o] -> LDS.128 fetches 4 output
// weights per tap (CC multiple of 4). Arithmetic identical to r12.
template<typename TIN, typename TOUT, int CIN, int CC, int C2, int MAXB>
__global__ void __launch_bounds__(256, MAXB)
k_down_f(const TIN* __restrict__ in, const float* __restrict__ w,
         const float* __restrict__ win,
         TOUT* __restrict__ out, float* __restrict__ t0,
         int Dd, int Hh, int Ww, int Hin, int Win) {
    extern __shared__ float sw[];
    const int NW1 = CC*CIN*27;
    const int NW2 = C2*(CC+CIN);
    // transpose: src o*(CIN*27) + k  ->  dst k*CC + o   (k = ic*27 + dz*9+dy*3+dx)
    for (int i = threadIdx.x; i < NW1; i += blockDim.x) {
        int o = i / (CIN*27);
        int k = i % (CIN*27);
        sw[k*CC + o] = w[i];
    }
    for (int i = threadIdx.x; i < NW2; i += blockDim.x) sw[NW1+i] = win[i];
    __syncthreads();
    const float* swin = sw + NW1;

    const int XQ = Ww/4;
    int N = Dd*Hh*Ww;
    int gid = blockIdx.x * blockDim.x + threadIdx.x;
    if (gid >= Dd*Hh*XQ) return;
    int xq = gid % XQ;
    int y  = (gid / XQ) % Hh;
    int z  = gid / (XQ*Hh);
    int x0 = xq * 4;
    size_t HWin = (size_t)Hin*Win;
    size_t Vin  = (size_t)(2*Dd)*HWin;
    bool lx = (x0 > 0);
    int outpos = (z*Hh + y)*Ww + x0;

    float acc[CC][4];
    #pragma unroll
    for (int o = 0; o < CC; o++)
        #pragma unroll
        for (int i = 0; i < 4; i++) acc[o][i] = 0.f;

    for (int ic = 0; ic < CIN; ic++) {
        const TIN* inp = in + (size_t)ic*Vin;
        float m[4] = {NEG_INF, NEG_INF, NEG_INF, NEG_INF};
        #pragma unroll
        for (int dz = 0; dz < 3; dz++) {
            int iz = 2*z - 1 + dz;
            if (iz < 0) continue;
            #pragma unroll
            for (int dy = 0; dy < 3; dy++) {
                int iy = 2*y - 1 + dy;
                if (iy < 0) continue;
                const TIN* r = inp + (size_t)iz*HWin + (size_t)iy*Win + 2*x0;
                float v[9];
                load_row9(r, lx, v);
                int wb = (ic*27 + dz*9 + dy*3)*CC;
                #pragma unroll
                for (int dx = 0; dx < 3; dx++) {
                    const float* wp = &sw[wb + dx*CC];
                    #pragma unroll
                    for (int o4 = 0; o4 < CC/4; o4++) {
                        float4 w4 = *(const float4*)(wp + o4*4);
                        #pragma unroll
                        for (int i = 0; i < 4; i++) {
                            float vv = v[2*i + dx];
                            acc[o4*4+0][i] = fmaf(w4.x, vv, acc[o4*4+0][i]);
                            acc[o4*4+1][i] = fmaf(w4.y, vv, acc[o4*4+1][i]);
                            acc[o4*4+2][i] = fmaf(w4.z, vv, acc[o4*4+2][i]);
                            acc[o4*4+3][i] = fmaf(w4.w, vv, acc[o4*4+3][i]);
                        }
                    }
                }
                if (dz > 0 && dy > 0) {
                    #pragma unroll
                    for (int i = 0; i < 4; i++)
                        m[i] = fmaxf(m[i], fmaxf(v[2*i+1], v[2*i+2]));
                }
            }
        }
        st4(out + (size_t)(CC + ic)*N + outpos,
            make_float4(fmaxf(m[0],0.f), fmaxf(m[1],0.f), fmaxf(m[2],0.f), fmaxf(m[3],0.f)));
    }

    float tac[C2][4];
    #pragma unroll
    for (int c = 0; c < C2; c++)
        #pragma unroll
        for (int i = 0; i < 4; i++) tac[c][i] = 0.f;

    #pragma unroll
    for (int o = 0; o < CC; o++) {
        float cv[4];
        #pragma unroll
        for (int i = 0; i < 4; i++) cv[i] = fmaxf(acc[o][i], 0.f);
        st4(out + (size_t)o*N + outpos, make_float4(cv[0],cv[1],cv[2],cv[3]));
        #pragma unroll
        for (int c = 0; c < C2; c++) {
            float wv = swin[c*(CC+CIN) + o];
            #pragma unroll
            for (int i = 0; i < 4; i++) tac[c][i] = fmaf(wv, cv[i], tac[c][i]);
        }
    }
    for (int ic = 0; ic < CIN; ic++) {
        float4 p4 = ld4f(out + (size_t)(CC + ic)*N + outpos);
        float p[4] = {p4.x, p4.y, p4.z, p4.w};
        #pragma unroll
        for (int c = 0; c < C2; c++) {
            float wv = swin[c*(CC+CIN) + CC + ic];
            #pragma unroll
            for (int i = 0; i < 4; i++) tac[c][i] = fmaf(wv, p[i], tac[c][i]);
        }
    }
    #pragma unroll
    for (int c = 0; c < C2; c++)
        st4(t0 + (size_t)c*N + outpos,
            make_float4(fmaxf(tac[c][0],0.f), fmaxf(tac[c][1],0.f),
                        fmaxf(tac[c][2],0.f), fmaxf(tac[c][3],0.f)));
}

// ---------------- vectorized bottleneck conv (fp32, r12 proven) ------------
template<int CIN, int COUT, int KD, int KH, int KW, bool ADD>
__global__ void k_conv3_v(const float* __restrict__ in, const float* __restrict__ w,
                          const float* __restrict__ bias, const float* __restrict__ add1,
                          float* __restrict__ out, int Dd, int Hh, int Ww) {
    constexpr int KSZ = KD*KH*KW;
    __shared__ float sw[COUT*CIN*KSZ];
    __shared__ float sb[COUT];
    for (int i = threadIdx.x; i < COUT*CIN*KSZ; i += blockDim.x) sw[i] = w[i];
    if (threadIdx.x < COUT) sb[threadIdx.x] = bias ? bias[threadIdx.x] : 0.f;
    __syncthreads();

    const int XQ = Ww/4;
    int N = Dd*Hh*Ww;
    int gid = blockIdx.x * blockDim.x + threadIdx.x;
    if (gid >= Dd*Hh*XQ) return;
    int xq = gid % XQ;
    int y  = (gid / XQ) % Hh;
    int z  = gid / (XQ*Hh);
    int x0 = xq * 4;
    bool lx = (x0 > 0), rxv = (x0 + 4 < Ww);
    int pos = (z*Hh + y)*Ww + x0;

    float acc[COUT][4];
    #pragma unroll
    for (int o = 0; o < COUT; o++)
        #pragma unroll
        for (int i = 0; i < 4; i++) acc[o][i] = sb[o];

    for (int ic = 0; ic < CIN; ic++) {
        const float* base = in + (size_t)ic*N;
        #pragma unroll
        for (int dz = 0; dz < KD; dz++) {
            int iz = z - KD/2 + dz;
            bool zv = ((unsigned)iz < (unsigned)Dd);
            #pragma unroll
            for (int dy = 0; dy < KH; dy++) {
                int iy = y - KH/2 + dy;
                bool rv = zv && ((unsigned)iy < (unsigned)Hh);
                const float* r = base + ((size_t)(zv?iz:0)*Hh + (rv?iy:0))*Ww + x0;
                float4 mv = rv ? *(const float4*)r : make_float4(0,0,0,0);
                if (KW == 3) {
                    float aE = (rv && lx)  ? r[-1] : 0.f;
                    float bE = (rv && rxv) ? r[4]  : 0.f;
                    float v[6] = {aE, mv.x, mv.y, mv.z, mv.w, bE};
                    #pragma unroll
                    for (int o = 0; o < COUT; o++) {
                        const float* wr = &sw[(o*CIN + ic)*KSZ + (dz*KH + dy)*KW];
                        float w0 = wr[0], w1 = wr[1], w2 = wr[2];
                        #pragma unroll
                        for (int i = 0; i < 4; i++)
                            acc[o][i] = fmaf(w0, v[i], fmaf(w1, v[i+1], fmaf(w2, v[i+2], acc[o][i])));
                    }
                } else {
                    float v[4] = {mv.x, mv.y, mv.z, mv.w};
                    #pragma unroll
                    for (int o = 0; o < COUT; o++) {
                        float wv = sw[(o*CIN + ic)*KSZ + (dz*KH + dy)];
                        #pragma unroll
                        for (int i = 0; i < 4; i++)
                            acc[o][i] = fmaf(wv, v[i], acc[o][i]);
                    }
                }
            }
        }
    }
    #pragma unroll
    for (int o = 0; o < COUT; o++) {
        float r4[4];
        #pragma unroll
        for (int i = 0; i < 4; i++) r4[i] = acc[o][i];
        if (ADD) {
            float4 ad = *(const float4*)(add1 + (size_t)o*N + pos);
            r4[0] += ad.x; r4[1] += ad.y; r4[2] += ad.z; r4[3] += ad.w;
        }
        *(float4*)(out + (size_t)o*N + pos) =
            make_float4(fmaxf(r4[0],0.f), fmaxf(r4[1],0.f), fmaxf(r4[2],0.f), fmaxf(r4[3],0.f));
    }
}

// ---------------- conv313 + 1x1 w_out + residual, fused --------------------
template<int CIN, int OC2, typename TR, typename TO>
__global__ void k_conv_out_v(const float* __restrict__ in, const float* __restrict__ w,
                             const float* __restrict__ bias,
                             const float* __restrict__ add1, const float* __restrict__ add2,
                             const float* __restrict__ wout, const TR* __restrict__ resid,
                             TO* __restrict__ out, int Dd, int Hh, int Ww) {
    __shared__ float sw[CIN*CIN*9];
    __shared__ float swo[OC2*CIN];
    __shared__ float sb[CIN];
    for (int i = threadIdx.x; i < CIN*CIN*9; i += blockDim.x) sw[i] = w[i];
    for (int i = threadIdx.x; i < OC2*CIN; i += blockDim.x) swo[i] = wout[i];
    if (threadIdx.x < CIN) sb[threadIdx.x] = bias[threadIdx.x];
    __syncthreads();

    const int XQ = Ww/4;
    int N = Dd*Hh*Ww;
    int gid = blockIdx.x * blockDim.x + threadIdx.x;
    if (gid >= Dd*Hh*XQ) return;
    int xq = gid % XQ;
    int y  = (gid / XQ) % Hh;
    int z  = gid / (XQ*Hh);
    int x0 = xq * 4;
    bool lx = (x0 > 0), rxv = (x0 + 4 < Ww);
    int pos = (z*Hh + y)*Ww + x0;

    float acc[CIN][4];
    #pragma unroll
    for (int o = 0; o < CIN; o++)
        #pragma unroll
        for (int i = 0; i < 4; i++) acc[o][i] = sb[o];

    for (int ic = 0; ic < CIN; ic++) {
        const float* base = in + (size_t)ic*N;
        #pragma unroll
        for (int dz = 0; dz < 3; dz++) {           // kernel (3,1,3)
            int iz = z - 1 + dz;
            bool rv = ((unsigned)iz < (unsigned)Dd);
            const float* r = base + ((size_t)(rv?iz:0)*Hh + y)*Ww + x0;
            float4 mv = rv ? *(const float4*)r : make_float4(0,0,0,0);
            float aE = (rv && lx)  ? r[-1] : 0.f;
            float bE = (rv && rxv) ? r[4]  : 0.f;
            float v[6] = {aE, mv.x, mv.y, mv.z, mv.w, bE};
            #pragma unroll
            for (int o = 0; o < CIN; o++) {
                const float* wr = &sw[(o*CIN + ic)*9 + dz*3];
                float w0 = wr[0], w1 = wr[1], w2 = wr[2];
                #pragma unroll
                for (int i = 0; i < 4; i++)
                    acc[o][i] = fmaf(w0, v[i], fmaf(w1, v[i+1], fmaf(w2, v[i+2], acc[o][i])));
            }
        }
    }
    float yv[CIN][4];
    #pragma unroll
    for (int o = 0; o < CIN; o++) {
        float4 a1 = *(const float4*)(add1 + (size_t)o*N + pos);
        float4 a2 = *(const float4*)(add2 + (size_t)o*N + pos);
        yv[o][0] = fmaxf(acc[o][0] + a1.x + a2.x, 0.f);
        yv[o][1] = fmaxf(acc[o][1] + a1.y + a2.y, 0.f);
        yv[o][2] = fmaxf(acc[o][2] + a1.z + a2.z, 0.f);
        yv[o][3] = fmaxf(acc[o][3] + a1.w + a2.w, 0.f);
    }
    #pragma unroll
    for (int o2 = 0; o2 < OC2; o2++) {
        float4 rr = ld4f(resid + (size_t)o2*N + pos);
        float s[4] = {rr.x, rr.y, rr.z, rr.w};
        #pragma unroll
        for (int c = 0; c < CIN; c++) {
            float wv = swo[o2*CIN + c];
            #pragma unroll
            for (int i = 0; i < 4; i++) s[i] = fmaf(wv, yv[c][i], s[i]);
        }
        st4(out + (size_t)o2*N + pos,
            make_float4(fmaxf(s[0],0.f), fmaxf(s[1],0.f), fmaxf(s[2],0.f), fmaxf(s[3],0.f)));
    }
}

// ---------------- launch ----------------
static inline int gridFor(long n, int b) { return (int)((n + b - 1) / b); }

extern "C" void kernel_launch(void* const* d_in, const int* in_sizes, int n_in,
                              void* d_out, int out_size) {
    const float* feat    = (const float*)d_in[0];
    const int*   depth   = (const int*)  d_in[1];
    const float* w_ds1   = (const float*)d_in[2];
    const float* b1_win  = (const float*)d_in[3];
    const float* b1_w133 = (const float*)d_in[4];
    const float* b1_b133 = (const float*)d_in[5];
    const float* b1_w331 = (const float*)d_in[6];
    const float* b1_b331 = (const float*)d_in[7];
    const float* b1_w313 = (const float*)d_in[8];
    const float* b1_b313 = (const float*)d_in[9];
    const float* b1_wout = (const float*)d_in[10];
    const float* w_ds2   = (const float*)d_in[11];
    const float* b2_win  = (const float*)d_in[12];
    const float* b2_w133 = (const float*)d_in[13];
    const float* b2_b133 = (const float*)d_in[14];
    const float* b2_w331 = (const float*)d_in[15];
    const float* b2_b331 = (const float*)d_in[16];
    const float* b2_w313 = (const float*)d_in[17];
    const float* b2_b313 = (const float*)d_in[18];
    const float* b2_wout = (const float*)d_in[19];
    float* out = (float*)d_out;

    void *a0,*a1,*a2,*a3,*a4,*a5,*a6,*a7,*a8,*a9;
    cudaGetSymbolAddress(&a0, g_filled);
    cudaGetSymbolAddress(&a1, g_ds1);
    cudaGetSymbolAddress(&a2, g_t0);
    cudaGetSymbolAddress(&a3, g_t1);
    cudaGetSymbolAddress(&a4, g_t2);
    cudaGetSymbolAddress(&a5, g_bn1);
    cudaGetSymbolAddress(&a6, g_ds2);
    cudaGetSymbolAddress(&a7, g_u0);
    cudaGetSymbolAddress(&a8, g_u1);
    cudaGetSymbolAddress(&a9, g_u2);
    __half* p_filled = (__half*)a0;
    __half* p_ds1 = (__half*)a1;
    float* p_t0  = (float*)a2; float* p_t1 = (float*)a3; float* p_t2 = (float*)a4;
    __half* p_bn1 = (__half*)a5;
    float* p_ds2 = (float*)a6;
    float* p_u0  = (float*)a7; float* p_u1 = (float*)a8; float* p_u2 = (float*)a9;

    // scatter stage
    k_init_w <<<gridFor(VV/4, 256), 256>>>();
    k_winner <<<gridFor(PIX, 256), 256>>>(depth);

    // avgpool fill via gather (fp16 output)
    k_fill_g<<<gridFor((long)C0*H0*(W0/4)*ZCH, 256), 256>>>(feat);

    // stage 1 (transposed-weight downsample)
    k_down_f<__half,__half,12,4,4,4><<<gridFor((long)D1*H1*(W1/4), 256), 256,
                                       (4*12*27 + 4*16)*sizeof(float)>>>(
        p_filled, w_ds1, b1_win, p_ds1, p_t0, D1, H1, W1, H0, W0);
    k_conv3_v<4,4,1,3,3,false><<<gridFor(N1/4, 256), 256>>>(
        p_t0, b1_w133, b1_b133, nullptr, p_t1, D1, H1, W1);
    k_conv3_v<4,4,3,3,1,true><<<gridFor(N1/4, 256), 256>>>(
        p_t1, b1_w331, b1_b331, p_t1, p_t2, D1, H1, W1);
    k_conv_out_v<4,16,__half,__half><<<gridFor(N1/4, 256), 256>>>(
        p_t2, b1_w313, b1_b313, p_t2, p_t1, b1_wout, p_ds1, p_bn1, D1, H1, W1);

    // stage 2 (transposed-weight downsample)
    k_down_f<__half,float,16,16,8,2><<<gridFor((long)D2*H2*(W2/4), 256), 256,
                                      (16*16*27 + 8*32)*sizeof(float)>>>(
        p_bn1, w_ds2, b2_win, p_ds2, p_u0, D2, H2, W2, H1, W1);
    k_conv3_v<8,8,1,3,3,false><<<gridFor(N2/4, 128), 128>>>(
        p_u0, b2_w133, b2_b133, nullptr, p_u1, D2, H2, W2);
    k_conv3_v<8,8,3,3,1,true><<<gridFor(N2/4, 128), 128>>>(
        p_u1, b2_w331, b2_b331, p_u1, p_u2, D2, H2, W2);
    k_conv_out_v<8,32,float,float><<<gridFor(N2/4, 128), 128>>>(
        p_u2, b2_w313, b2_b313, p_u2, p_u1, b2_wout, p_ds2, out, D2, H2, W2);
}

// round 17
// speedup vs baseline: 1.0590x; 1.0089x over previous
#include <cuda_runtime.h>
#include <cuda_fp16.h>
#include <cstdint>

// ---------------- problem constants ----------------
#define C0   12
#define D0   240
#define H0   144
#define W0   240
#define HW0  (H0*W0)
#define VV   (D0*H0*W0)          // 8,294,400 voxels
#define PIX  (480*640)           // 307,200 pixels

#define D1 120
#define H1 72
#define W1 120
#define N1 (D1*H1*W1)

#define D2 60
#define H2 36
#define W2 60
#define N2 (D2*H2*W2)

#define ZCH 12
#define ZL  (D0/ZCH)             // 20

#define NEG_INF (__int_as_float(0xff800000))

// ---------------- scratch ----------------
__device__ __half g_filled[(size_t)C0*VV];   // fp16
__device__ int    g_winner[VV];
__device__ __half g_ds1[(size_t)16*N1];      // fp16
__device__ float  g_t0[(size_t)4*N1];
__device__ float  g_t1[(size_t)4*N1];
__device__ float  g_t2[(size_t)4*N1];
__device__ __half g_bn1[(size_t)16*N1];      // fp16
__device__ float  g_ds2[(size_t)32*N2];
__device__ float  g_u0[(size_t)8*N2];
__device__ float  g_u1[(size_t)8*N2];
__device__ float  g_u2[(size_t)8*N2];

// ---------------- generic load/store helpers ----------------
__device__ __forceinline__ float4 ld4f(const float* p) { return *(const float4*)p; }
__device__ __forceinline__ float4 ld4f(const __half* p) {
    uint2 u = *(const uint2*)p;
    float2 a = __half22float2(*reinterpret_cast<const __half2*>(&u.x));
    float2 b = __half22float2(*reinterpret_cast<const __half2*>(&u.y));
    return make_float4(a.x, a.y, b.x, b.y);
}
__device__ __forceinline__ void st4(float* p, float4 v) { *(float4*)p = v; }
__device__ __forceinline__ void st4(__half* p, float4 v) {
    union { __half2 h[2]; uint2 u; } pk_;
    pk_.h[0] = __floats2half2_rn(v.x, v.y);
    pk_.h[1] = __floats2half2_rn(v.z, v.w);
    *(uint2*)p = pk_.u;
}

// 9-value row loaders (zero-padded left edge)
__device__ __forceinline__ void load_row9(const float* r, bool lx, float v[9]) {
    float4 a = *(const float4*)r;
    float4 b = *(const float4*)(r + 4);
    v[0] = lx ? r[-1] : 0.f;
    v[1]=a.x; v[2]=a.y; v[3]=a.z; v[4]=a.w;
    v[5]=b.x; v[6]=b.y; v[7]=b.z; v[8]=b.w;
}
__device__ __forceinline__ void load_row9(const __half* r, bool lx, float v[9]) {
    uint4 u = *(const uint4*)r;          // 8 halves, 16B-aligned
    float2 p0 = __half22float2(*reinterpret_cast<const __half2*>(&u.x));
    float2 p1 = __half22float2(*reinterpret_cast<const __half2*>(&u.y));
    float2 p2 = __half22float2(*reinterpret_cast<const __half2*>(&u.z));
    float2 p3 = __half22float2(*reinterpret_cast<const __half2*>(&u.w));
    v[0] = lx ? __half2float(r[-1]) : 0.f;
    v[1]=p0.x; v[2]=p0.y; v[3]=p1.x; v[4]=p1.y;
    v[5]=p2.x; v[6]=p2.y; v[7]=p3.x; v[8]=p3.y;
}

// ---------------- scatter stage ----------------
__global__ void k_init_w() {
    int i = blockIdx.x * blockDim.x + threadIdx.x;
    if (i < VV/4) ((int4*)g_winner)[i] = make_int4(-1,-1,-1,-1);
}

__global__ void k_winner(const int* __restrict__ depth) {
    int p = blockIdx.x * blockDim.x + threadIdx.x;
    if (p >= PIX) return;
    int d = depth[p];
    if (d > 0) atomicMax(&g_winner[d], p);
}

// ---------------- avgpool fill, gather version (ZCH=12, fp16 output) -------
__global__ void k_fill_g(const float* __restrict__ feat) {
    const int XQ = W0/4;   // 60
    int gid = blockIdx.x * blockDim.x + threadIdx.x;
    if (gid >= C0*H0*XQ*ZCH) return;
    int xq = gid % XQ;
    int y  = (gid / XQ) % H0;
    int zc = (gid / (XQ*H0)) % ZCH;
    int c  = gid / (XQ*H0*ZCH);
    int x0 = xq * 4;
    int z0 = zc * ZL;

    const int*   wbase = g_winner;
    const float* featc = feat + (size_t)c*PIX;
    __half*      outb  = g_filled + (size_t)c*VV;

    bool ym0 = (y > 0), ym2 = (y < H0-1);
    int ro0 = (y-1)*W0 + x0;
    int ro1 =  y   *W0 + x0;
    int ro2 = (y+1)*W0 + x0;
    bool lx = (x0 > 0), rx = (x0 + 4 < W0);

    auto val = [&](int wv) -> float {
        return (wv >= 0) ? __ldg(featc + wv) : 0.f;
    };

    auto plane = [&](int z, float4& s, float4& ctr) {
        const int* pl = wbase + (size_t)z*HW0;
        s = make_float4(0.f,0.f,0.f,0.f);
        #pragma unroll
        for (int dy = 0; dy < 3; dy++) {
            if (dy == 0 && !ym0) continue;
            if (dy == 2 && !ym2) continue;
            const int* r = pl + (dy == 0 ? ro0 : (dy == 1 ? ro1 : ro2));
            int4 mi = *(const int4*)r;
            float m0 = val(mi.x), m1 = val(mi.y), m2 = val(mi.z), m3 = val(mi.w);
            float a = lx ? val(__ldg(r-1)) : 0.f;
            float b = rx ? val(__ldg(r+4)) : 0.f;
            s.x += a  + m0 + m1;
            s.y += m0 + m1 + m2;
            s.z += m1 + m2 + m3;
            s.w += m2 + m3 + b;
            if (dy == 1) ctr = make_float4(m0, m1, m2, m3);
        }
    };

    float4 sp, sc, sn, cc_, cn, dum;
    const float4 z4 = make_float4(0.f,0.f,0.f,0.f);
    if (z0 > 0) plane(z0-1, sp, dum); else sp = z4;
    plane(z0, sc, cc_);
    for (int z = z0; z < z0 + ZL; z++) {
        if (z + 1 < D0) plane(z+1, sn, cn); else { sn = z4; cn = z4; }
        float4 o;
        o.x = (cc_.x == 0.f) ? (sp.x+sc.x+sn.x) * (1.f/27.f) : cc_.x;
        o.y = (cc_.y == 0.f) ? (sp.y+sc.y+sn.y) * (1.f/27.f) : cc_.y;
        o.z = (cc_.z == 0.f) ? (sp.z+sc.z+sn.z) * (1.f/27.f) : cc_.z;
        o.w = (cc_.w == 0.f) ? (sp.w+sc.w+sn.w) * (1.f/27.f) : cc_.w;
        st4(outb + (size_t)z*HW0 + ro1, o);
        sp = sc; sc = sn; cc_ = cn;
    }
}

// ---------------- fused downsample + 1x1 w_in (transposed weights, r16) ----
template<typename TIN, typename TOUT, int CIN, int CC, int C2, int MAXB>
__global__ void __launch_bounds__(256, MAXB)
k_down_f(const TIN* __restrict__ in, const float* __restrict__ w,
         const float* __restrict__ win,
         TOUT* __restrict__ out, float* __restrict__ t0,
         int Dd, int Hh, int Ww, int Hin, int Win) {
    extern __shared__ float sw[];
    const int NW1 = CC*CIN*27;
    const int NW2 = C2*(CC+CIN);
    for (int i = threadIdx.x; i < NW1; i += blockDim.x) {
        int o = i / (CIN*27);
        int k = i % (CIN*27);
        sw[k*CC + o] = w[i];
    }
    for (int i = threadIdx.x; i < NW2; i += blockDim.x) sw[NW1+i] = win[i];
    __syncthreads();
    const float* swin = sw + NW1;

    const int XQ = Ww/4;
    int N = Dd*Hh*Ww;
    int gid = blockIdx.x * blockDim.x + threadIdx.x;
    if (gid >= Dd*Hh*XQ) return;
    int xq = gid % XQ;
    int y  = (gid / XQ) % Hh;
    int z  = gid / (XQ*Hh);
    int x0 = xq * 4;
    size_t HWin = (size_t)Hin*Win;
    size_t Vin  = (size_t)(2*Dd)*HWin;
    bool lx = (x0 > 0);
    int outpos = (z*Hh + y)*Ww + x0;

    float acc[CC][4];
    #pragma unroll
    for (int o = 0; o < CC; o++)
        #pragma unroll
        for (int i = 0; i < 4; i++) acc[o][i] = 0.f;

    for (int ic = 0; ic < CIN; ic++) {
        const TIN* inp = in + (size_t)ic*Vin;
        float m[4] = {NEG_INF, NEG_INF, NEG_INF, NEG_INF};
        #pragma unroll
        for (int dz = 0; dz < 3; dz++) {
            int iz = 2*z - 1 + dz;
            if (iz < 0) continue;
            #pragma unroll
            for (int dy = 0; dy < 3; dy++) {
                int iy = 2*y - 1 + dy;
                if (iy < 0) continue;
                const TIN* r = inp + (size_t)iz*HWin + (size_t)iy*Win + 2*x0;
                float v[9];
                load_row9(r, lx, v);
                int wb = (ic*27 + dz*9 + dy*3)*CC;
                #pragma unroll
                for (int dx = 0; dx < 3; dx++) {
                    const float* wp = &sw[wb + dx*CC];
                    #pragma unroll
                    for (int o4 = 0; o4 < CC/4; o4++) {
                        float4 w4 = *(const float4*)(wp + o4*4);
                        #pragma unroll
                        for (int i = 0; i < 4; i++) {
                            float vv = v[2*i + dx];
                            acc[o4*4+0][i] = fmaf(w4.x, vv, acc[o4*4+0][i]);
                            acc[o4*4+1][i] = fmaf(w4.y, vv, acc[o4*4+1][i]);
                            acc[o4*4+2][i] = fmaf(w4.z, vv, acc[o4*4+2][i]);
                            acc[o4*4+3][i] = fmaf(w4.w, vv, acc[o4*4+3][i]);
                        }
                    }
                }
                if (dz > 0 && dy > 0) {
                    #pragma unroll
                    for (int i = 0; i < 4; i++)
                        m[i] = fmaxf(m[i], fmaxf(v[2*i+1], v[2*i+2]));
                }
            }
        }
        st4(out + (size_t)(CC + ic)*N + outpos,
            make_float4(fmaxf(m[0],0.f), fmaxf(m[1],0.f), fmaxf(m[2],0.f), fmaxf(m[3],0.f)));
    }

    float tac[C2][4];
    #pragma unroll
    for (int c = 0; c < C2; c++)
        #pragma unroll
        for (int i = 0; i < 4; i++) tac[c][i] = 0.f;

    #pragma unroll
    for (int o = 0; o < CC; o++) {
        float cv[4];
        #pragma unroll
        for (int i = 0; i < 4; i++) cv[i] = fmaxf(acc[o][i], 0.f);
        st4(out + (size_t)o*N + outpos, make_float4(cv[0],cv[1],cv[2],cv[3]));
        #pragma unroll
        for (int c = 0; c < C2; c++) {
            float wv = swin[c*(CC+CIN) + o];
            #pragma unroll
            for (int i = 0; i < 4; i++) tac[c][i] = fmaf(wv, cv[i], tac[c][i]);
        }
    }
    for (int ic = 0; ic < CIN; ic++) {
        float4 p4 = ld4f(out + (size_t)(CC + ic)*N + outpos);
        float p[4] = {p4.x, p4.y, p4.z, p4.w};
        #pragma unroll
        for (int c = 0; c < C2; c++) {
            float wv = swin[c*(CC+CIN) + CC + ic];
            #pragma unroll
            for (int i = 0; i < 4; i++) tac[c][i] = fmaf(wv, p[i], tac[c][i]);
        }
    }
    #pragma unroll
    for (int c = 0; c < C2; c++)
        st4(t0 + (size_t)c*N + outpos,
            make_float4(fmaxf(tac[c][0],0.f), fmaxf(tac[c][1],0.f),
                        fmaxf(tac[c][2],0.f), fmaxf(tac[c][3],0.f)));
}

// ---------------- bottleneck conv (transposed weights) ---------------------
// smem layout [k][o], k = ic*KSZ + (dz*KH+dy)*KW + dx; float4 weight fetch.
template<int CIN, int COUT, int KD, int KH, int KW, bool ADD>
__global__ void k_conv3_v(const float* __restrict__ in, const float* __restrict__ w,
                          const float* __restrict__ bias, const float* __restrict__ add1,
                          float* __restrict__ out, int Dd, int Hh, int Ww) {
    constexpr int KSZ = KD*KH*KW;
    __shared__ float sw[COUT*CIN*KSZ];
    __shared__ float sb[COUT];
    for (int i = threadIdx.x; i < COUT*CIN*KSZ; i += blockDim.x) {
        int o = i / (CIN*KSZ);
        int k = i % (CIN*KSZ);
        sw[k*COUT + o] = w[i];
    }
    if (threadIdx.x < COUT) sb[threadIdx.x] = bias ? bias[threadIdx.x] : 0.f;
    __syncthreads();

    const int XQ = Ww/4;
    int N = Dd*Hh*Ww;
    int gid = blockIdx.x * blockDim.x + threadIdx.x;
    if (gid >= Dd*Hh*XQ) return;
    int xq = gid % XQ;
    int y  = (gid / XQ) % Hh;
    int z  = gid / (XQ*Hh);
    int x0 = xq * 4;
    bool lx = (x0 > 0), rxv = (x0 + 4 < Ww);
    int pos = (z*Hh + y)*Ww + x0;

    float acc[COUT][4];
    #pragma unroll
    for (int o = 0; o < COUT; o++)
        #pragma unroll
        for (int i = 0; i < 4; i++) acc[o][i] = sb[o];

    for (int ic = 0; ic < CIN; ic++) {
        const float* base = in + (size_t)ic*N;
        #pragma unroll
        for (int dz = 0; dz < KD; dz++) {
            int iz = z - KD/2 + dz;
            bool zv = ((unsigned)iz < (unsigned)Dd);
            #pragma unroll
            for (int dy = 0; dy < KH; dy++) {
                int iy = y - KH/2 + dy;
                bool rv = zv && ((unsigned)iy < (unsigned)Hh);
                const float* r = base + ((size_t)(zv?iz:0)*Hh + (rv?iy:0))*Ww + x0;
                float4 mv = rv ? *(const float4*)r : make_float4(0,0,0,0);
                int kb = ic*KSZ + (dz*KH + dy)*KW;
                if (KW == 3) {
                    float aE = (rv && lx)  ? r[-1] : 0.f;
                    float bE = (rv && rxv) ? r[4]  : 0.f;
                    float v[6] = {aE, mv.x, mv.y, mv.z, mv.w, bE};
                    #pragma unroll
                    for (int dx = 0; dx < 3; dx++) {
                        const float* wp = &sw[(kb + dx)*COUT];
                        #pragma unroll
                        for (int o4 = 0; o4 < COUT/4; o4++) {
                            float4 w4 = *(const float4*)(wp + o4*4);
                            #pragma unroll
                            for (int i = 0; i < 4; i++) {
                                float vv = v[i + dx];
                                acc[o4*4+0][i] = fmaf(w4.x, vv, acc[o4*4+0][i]);
                                acc[o4*4+1][i] = fmaf(w4.y, vv, acc[o4*4+1][i]);
                                acc[o4*4+2][i] = fmaf(w4.z, vv, acc[o4*4+2][i]);
                                acc[o4*4+3][i] = fmaf(w4.w, vv, acc[o4*4+3][i]);
                            }
                        }
                    }
                } else {
                    float v[4] = {mv.x, mv.y, mv.z, mv.w};
                    const float* wp = &sw[kb*COUT];
                    #pragma unroll
                    for (int o4 = 0; o4 < COUT/4; o4++) {
                        float4 w4 = *(const float4*)(wp + o4*4);
                        #pragma unroll
                        for (int i = 0; i < 4; i++) {
                            acc[o4*4+0][i] = fmaf(w4.x, v[i], acc[o4*4+0][i]);
                            acc[o4*4+1][i] = fmaf(w4.y, v[i], acc[o4*4+1][i]);
                            acc[o4*4+2][i] = fmaf(w4.z, v[i], acc[o4*4+2][i]);
                            acc[o4*4+3][i] = fmaf(w4.w, v[i], acc[o4*4+3][i]);
                        }
                    }
                }
            }
        }
    }
    #pragma unroll
    for (int o = 0; o < COUT; o++) {
        float r4[4];
        #pragma unroll
        for (int i = 0; i < 4; i++) r4[i] = acc[o][i];
        if (ADD) {
            float4 ad = *(const float4*)(add1 + (size_t)o*N + pos);
            r4[0] += ad.x; r4[1] += ad.y; r4[2] += ad.z; r4[3] += ad.w;
        }
        *(float4*)(out + (size_t)o*N + pos) =
            make_float4(fmaxf(r4[0],0.f), fmaxf(r4[1],0.f), fmaxf(r4[2],0.f), fmaxf(r4[3],0.f));
    }
}

// ---------------- conv313 + 1x1 w_out + residual (transposed weights) ------
template<int CIN, int OC2, typename TR, typename TO>
__global__ void k_conv_out_v(const float* __restrict__ in, const float* __restrict__ w,
                             const float* __restrict__ bias,
                             const float* __restrict__ add1, const float* __restrict__ add2,
                             const float* __restrict__ wout, const TR* __restrict__ resid,
                             TO* __restrict__ out, int Dd, int Hh, int Ww) {
    __shared__ float sw[CIN*CIN*9];
    __shared__ float swo[OC2*CIN];
    __shared__ float sb[CIN];
    for (int i = threadIdx.x; i < CIN*CIN*9; i += blockDim.x) {
        int o = i / (CIN*9);
        int k = i % (CIN*9);     // k = ic*9 + dz*3 + dx
        sw[k*CIN + o] = w[i];
    }
    for (int i = threadIdx.x; i < OC2*CIN; i += blockDim.x) swo[i] = wout[i];
    if (threadIdx.x < CIN) sb[threadIdx.x] = bias[threadIdx.x];
    __syncthreads();

    const int XQ = Ww/4;
    int N = Dd*Hh*Ww;
    int gid = blockIdx.x * blockDim.x + threadIdx.x;
    if (gid >= Dd*Hh*XQ) return;
    int xq = gid % XQ;
    int y  = (gid / XQ) % Hh;
    int z  = gid / (XQ*Hh);
    int x0 = xq * 4;
    bool lx = (x0 > 0), rxv = (x0 + 4 < Ww);
    int pos = (z*Hh + y)*Ww + x0;

    float acc[CIN][4];
    #pragma unroll
    for (int o = 0; o < CIN; o++)
        #pragma unroll
        for (int i = 0; i < 4; i++) acc[o][i] = sb[o];

    for (int ic = 0; ic < CIN; ic++) {
        const float* base = in + (size_t)ic*N;
        #pragma unroll
        for (int dz = 0; dz < 3; dz++) {           // kernel (3,1,3)
            int iz = z - 1 + dz;
            bool rv = ((unsigned)iz < (unsigned)Dd);
            const float* r = base + ((size_t)(rv?iz:0)*Hh + y)*Ww + x0;
            float4 mv = rv ? *(const float4*)r : make_float4(0,0,0,0);
            float aE = (rv && lx)  ? r[-1] : 0.f;
            float bE = (rv && rxv) ? r[4]  : 0.f;
            float v[6] = {aE, mv.x, mv.y, mv.z, mv.w, bE};
            int kb = ic*9 + dz*3;
            #pragma unroll
            for (int dx = 0; dx < 3; dx++) {
                const float* wp = &sw[(kb + dx)*CIN];
                #pragma unroll
                for (int o4 = 0; o4 < CIN/4; o4++) {
                    float4 w4 = *(const float4*)(wp + o4*4);
                    #pragma unroll
                    for (int i = 0; i < 4; i++) {
                        float vv = v[i + dx];
                        acc[o4*4+0][i] = fmaf(w4.x, vv, acc[o4*4+0][i]);
                        acc[o4*4+1][i] = fmaf(w4.y, vv, acc[o4*4+1][i]);
                        acc[o4*4+2][i] = fmaf(w4.z, vv, acc[o4*4+2][i]);
                        acc[o4*4+3][i] = fmaf(w4.w, vv, acc[o4*4+3][i]);
                    }
                }
            }
        }
    }
    float yv[CIN][4];
    #pragma unroll
    for (int o = 0; o < CIN; o++) {
        float4 a1 = *(const float4*)(add1 + (size_t)o*N + pos);
        float4 a2 = *(const float4*)(add2 + (size_t)o*N + pos);
        yv[o][0] = fmaxf(acc[o][0] + a1.x + a2.x, 0.f);
        yv[o][1] = fmaxf(acc[o][1] + a1.y + a2.y, 0.f);
        yv[o][2] = fmaxf(acc[o][2] + a1.z + a2.z, 0.f);
        yv[o][3] = fmaxf(acc[o][3] + a1.w + a2.w, 0.f);
    }
    #pragma unroll
    for (int o2 = 0; o2 < OC2; o2++) {
        float4 rr = ld4f(resid + (size_t)o2*N + pos);
        float s[4] = {rr.x, rr.y, rr.z, rr.w};
        #pragma unroll
        for (int c = 0; c < CIN; c++) {
            float wv = swo[o2*CIN + c];
            #pragma unroll
            for (int i = 0; i < 4; i++) s[i] = fmaf(wv, yv[c][i], s[i]);
        }
        st4(out + (size_t)o2*N + pos,
            make_float4(fmaxf(s[0],0.f), fmaxf(s[1],0.f), fmaxf(s[2],0.f), fmaxf(s[3],0.f)));
    }
}

// ---------------- launch ----------------
static inline int gridFor(long n, int b) { return (int)((n + b - 1) / b); }

extern "C" void kernel_launch(void* const* d_in, const int* in_sizes, int n_in,
                              void* d_out, int out_size) {
    const float* feat    = (const float*)d_in[0];
    const int*   depth   = (const int*)  d_in[1];
    const float* w_ds1   = (const float*)d_in[2];
    const float* b1_win  = (const float*)d_in[3];
    const float* b1_w133 = (const float*)d_in[4];
    const float* b1_b133 = (const float*)d_in[5];
    const float* b1_w331 = (const float*)d_in[6];
    const float* b1_b331 = (const float*)d_in[7];
    const float* b1_w313 = (const float*)d_in[8];
    const float* b1_b313 = (const float*)d_in[9];
    const float* b1_wout = (const float*)d_in[10];
    const float* w_ds2   = (const float*)d_in[11];
    const float* b2_win  = (const float*)d_in[12];
    const float* b2_w133 = (const float*)d_in[13];
    const float* b2_b133 = (const float*)d_in[14];
    const float* b2_w331 = (const float*)d_in[15];
    const float* b2_b331 = (const float*)d_in[16];
    const float* b2_w313 = (const float*)d_in[17];
    const float* b2_b313 = (const float*)d_in[18];
    const float* b2_wout = (const float*)d_in[19];
    float* out = (float*)d_out;

    void *a0,*a1,*a2,*a3,*a4,*a5,*a6,*a7,*a8,*a9;
    cudaGetSymbolAddress(&a0, g_filled);
    cudaGetSymbolAddress(&a1, g_ds1);
    cudaGetSymbolAddress(&a2, g_t0);
    cudaGetSymbolAddress(&a3, g_t1);
    cudaGetSymbolAddress(&a4, g_t2);
    cudaGetSymbolAddress(&a5, g_bn1);
    cudaGetSymbolAddress(&a6, g_ds2);
    cudaGetSymbolAddress(&a7, g_u0);
    cudaGetSymbolAddress(&a8, g_u1);
    cudaGetSymbolAddress(&a9, g_u2);
    __half* p_filled = (__half*)a0;
    __half* p_ds1 = (__half*)a1;
    float* p_t0  = (float*)a2; float* p_t1 = (float*)a3; float* p_t2 = (float*)a4;
    __half* p_bn1 = (__half*)a5;
    float* p_ds2 = (float*)a6;
    float* p_u0  = (float*)a7; float* p_u1 = (float*)a8; float* p_u2 = (float*)a9;

    // scatter stage
    k_init_w <<<gridFor(VV/4, 256), 256>>>();
    k_winner <<<gridFor(PIX, 256), 256>>>(depth);

    // avgpool fill via gather (fp16 output)
    k_fill_g<<<gridFor((long)C0*H0*(W0/4)*ZCH, 256), 256>>>(feat);

    // stage 1
    k_down_f<__half,__half,12,4,4,4><<<gridFor((long)D1*H1*(W1/4), 256), 256,
                                       (4*12*27 + 4*16)*sizeof(float)>>>(
        p_filled, w_ds1, b1_win, p_ds1, p_t0, D1, H1, W1, H0, W0);
    k_conv3_v<4,4,1,3,3,false><<<gridFor(N1/4, 256), 256>>>(
        p_t0, b1_w133, b1_b133, nullptr, p_t1, D1, H1, W1);
    k_conv3_v<4,4,3,3,1,true><<<gridFor(N1/4, 256), 256>>>(
        p_t1, b1_w331, b1_b331, p_t1, p_t2, D1, H1, W1);
    k_conv_out_v<4,16,__half,__half><<<gridFor(N1/4, 256), 256>>>(
        p_t2, b1_w313, b1_b313, p_t2, p_t1, b1_wout, p_ds1, p_bn1, D1, H1, W1);

    // stage 2
    k_down_f<__half,float,16,16,8,2><<<gridFor((long)D2*H2*(W2/4), 256), 256,
                                      (16*16*27 + 8*32)*sizeof(float)>>>(
        p_bn1, w_ds2, b2_win, p_ds2, p_u0, D2, H2, W2, H1, W1);
    k_conv3_v<8,8,1,3,3,false><<<gridFor(N2/4, 128), 128>>>(
        p_u0, b2_w133, b2_b133, nullptr, p_u1, D2, H2, W2);
    k_conv3_v<8,8,3,3,1,true><<<gridFor(N2/4, 128), 128>>>(
        p_u1, b2_w331, b2_b331, p_u1, p_u2, D2, H2, W2);
    k_conv_out_v<8,32,float,float><<<gridFor(N2/4, 128), 128>>>(
        p_u2, b2_w313, b2_b313, p_u2, p_u1, b2_wout, p_ds2, out, D2, H2, W2);
}